// round 6
// baseline (speedup 1.0000x reference)
#include <cuda_runtime.h>
#include <cstdint>

// Problem constants (fixed shapes from reference)
static constexpr long long N  = 100000;   // nodes
static constexpr long long E  = 3200000;  // edges
static constexpr long long D  = 256;      // node feat
static constexpr long long De = 32;       // edge feat
static constexpr long long B  = 128;      // graphs

// Region chunk counts, float4 (16B) units. All boundaries are %4==0 floats.
// Order: 0:x copy 1:x zero 2:ei_r0 3:heads 4:ei_r1 5:tails 6:ea copy 7:ea zero 8:batch 9:arangeB
static constexpr long long C0 = N * D / 4;    //  6,400,000
static constexpr long long C1 = B * D / 4;    //      8,192
static constexpr long long C2 = E / 4;        //    800,000
static constexpr long long C3 = N / 4;        //     25,000
static constexpr long long C4 = E / 4;
static constexpr long long C5 = N / 4;
static constexpr long long C6 = E * De / 4;   // 25,600,000
static constexpr long long C7 = N * De / 4;   //    800,000
static constexpr long long C8 = N / 4;
static constexpr long long C9 = B / 4;        //         32

// Output bases (prefix sums, float4 units)
static constexpr long long O0 = 0;
static constexpr long long O1 = O0 + C0;
static constexpr long long O2 = O1 + C1;
static constexpr long long O3 = O2 + C2;
static constexpr long long O4 = O3 + C3;
static constexpr long long O5 = O4 + C4;
static constexpr long long O6 = O5 + C5;
static constexpr long long O7 = O6 + C6;
static constexpr long long O8 = O7 + C7;
static constexpr long long O9 = O8 + C8;

static constexpr int T = 256;
static constexpr int UNROLL = 8;
static constexpr long long CPB = (long long)T * UNROLL;  // 2048 chunks/block

static constexpr long long cdiv(long long a, long long b) { return (a + b - 1) / b; }
static constexpr long long B0 = cdiv(C0, CPB);
static constexpr long long B1 = cdiv(C1, CPB);
static constexpr long long B2 = cdiv(C2, CPB);
static constexpr long long B3 = cdiv(C3, CPB);
static constexpr long long B4 = cdiv(C4, CPB);
static constexpr long long B5 = cdiv(C5, CPB);
static constexpr long long B6 = cdiv(C6, CPB);
static constexpr long long B7 = cdiv(C7, CPB);
static constexpr long long B8 = cdiv(C8, CPB);
static constexpr long long B9 = cdiv(C9, CPB);
// Block-range prefix
static constexpr long long P0 = 0;
static constexpr long long P1 = P0 + B0;
static constexpr long long P2 = P1 + B1;
static constexpr long long P3 = P2 + B2;
static constexpr long long P4 = P3 + B3;
static constexpr long long P5 = P4 + B4;
static constexpr long long P6 = P5 + B5;
static constexpr long long P7 = P6 + B6;
static constexpr long long P8 = P7 + B7;
static constexpr long long P9 = P8 + B8;
static constexpr long long P_END = P9 + B9;

__global__ void __launch_bounds__(T) vnode_fused_kernel(
    const float* __restrict__ x, const int* __restrict__ ei,
    const float* __restrict__ ea, const int* __restrict__ batch,
    float* __restrict__ out, long long out_lim)
{
    // Device-local lookup tables (constexpr scalars fold fine; arrays must be local)
    const long long PFX[11]  = {P0,P1,P2,P3,P4,P5,P6,P7,P8,P9,P_END};
    const long long CHN[10]  = {C0,C1,C2,C3,C4,C5,C6,C7,C8,C9};
    const long long OBS[10]  = {O0,O1,O2,O3,O4,O5,O6,O7,O8,O9};

    const long long b = blockIdx.x;

    // Resolve region once per block (uniform compare chain on blockIdx).
    int r = 0;
#pragma unroll
    for (int k = 1; k < 10; k++)
        if (b >= PFX[k]) r = k;

    const long long nch   = CHN[r];
    const long long obase = OBS[r];
    const long long c0 = (b - PFX[r]) * CPB + threadIdx.x;  // region-local chunk idx
    const long long lim4 = out_lim / 4;

    long long c[UNROLL];
    bool ok[UNROLL];
#pragma unroll
    for (int k = 0; k < UNROLL; k++) {
        c[k] = c0 + (long long)k * T;
        ok[k] = (c[k] < nch) && (obase + c[k] < lim4);
    }

    float4 v[UNROLL];

    switch (r) {
    case 0: {  // x copy
        const float4* src = (const float4*)x;
#pragma unroll
        for (int k = 0; k < UNROLL; k++) if (ok[k]) v[k] = __ldcs(src + c[k]);
        break;
    }
    case 6: {  // ea copy (74% of blocks)
        const float4* src = (const float4*)ea;
#pragma unroll
        for (int k = 0; k < UNROLL; k++) if (ok[k]) v[k] = __ldcs(src + c[k]);
        break;
    }
    case 1: case 7: {  // zeros
#pragma unroll
        for (int k = 0; k < UNROLL; k++) v[k] = make_float4(0.f, 0.f, 0.f, 0.f);
        break;
    }
    case 2: {  // ei row 0: int -> float
        const int4* src = (const int4*)ei;
#pragma unroll
        for (int k = 0; k < UNROLL; k++) if (ok[k]) {
            int4 a = __ldcs(src + c[k]);
            v[k] = make_float4((float)a.x, (float)a.y, (float)a.z, (float)a.w);
        }
        break;
    }
    case 4: {  // ei row 1: int -> float
        const int4* src = (const int4*)(ei + E);
#pragma unroll
        for (int k = 0; k < UNROLL; k++) if (ok[k]) {
            int4 a = __ldcs(src + c[k]);
            v[k] = make_float4((float)a.x, (float)a.y, (float)a.z, (float)a.w);
        }
        break;
    }
    case 3: case 9: {  // arange (heads / arange(B))
#pragma unroll
        for (int k = 0; k < UNROLL; k++) {
            float f = (float)(4 * c[k]);
            v[k] = make_float4(f, f + 1.f, f + 2.f, f + 3.f);
        }
        break;
    }
    case 5: {  // tails = N + batch
        const int4* src = (const int4*)batch;
#pragma unroll
        for (int k = 0; k < UNROLL; k++) if (ok[k]) {
            int4 a = __ldcs(src + c[k]);
            v[k] = make_float4((float)(N + a.x), (float)(N + a.y),
                               (float)(N + a.z), (float)(N + a.w));
        }
        break;
    }
    default: {  // case 8: new_batch head = batch cast
        const int4* src = (const int4*)batch;
#pragma unroll
        for (int k = 0; k < UNROLL; k++) if (ok[k]) {
            int4 a = __ldcs(src + c[k]);
            v[k] = make_float4((float)a.x, (float)a.y, (float)a.z, (float)a.w);
        }
        break;
    }
    }

    float4* dst = (float4*)out + obase;
#pragma unroll
    for (int k = 0; k < UNROLL; k++)
        if (ok[k]) __stcs(dst + c[k], v[k]);
}

extern "C" void kernel_launch(void* const* d_in, const int* in_sizes, int n_in,
                              void* d_out, int out_size) {
    const float* x     = (const float*)d_in[0];
    const int*   ei    = (const int*)d_in[1];
    const float* ea    = (const float*)d_in[2];
    const int*   batch = (const int*)d_in[3];
    float* out = (float*)d_out;

    vnode_fused_kernel<<<(unsigned)P_END, T>>>(x, ei, ea, batch, out, (long long)out_size);
}

// round 8
// speedup vs baseline: 1.3878x; 1.3878x over previous
#include <cuda_runtime.h>
#include <cstdint>

// R8 = R7 resubmitted unchanged (R7 failed with cudaErrorSystemNotReady at
// harness context init — broker-side transient, kernel never ran).

// Problem constants (fixed shapes from reference)
static constexpr long long N  = 100000;   // nodes
static constexpr long long E  = 3200000;  // edges
static constexpr long long D  = 256;      // node feat
static constexpr long long De = 32;       // edge feat
static constexpr long long B  = 128;      // graphs

// Region chunk counts, float4 (16B) units. All boundaries are %4==0 floats.
// Order: 0:x copy 1:x zero 2:ei_r0 3:heads 4:ei_r1 5:tails 6:ea copy 7:ea zero 8:batch 9:arangeB
static constexpr unsigned C0 = (unsigned)(N * D / 4);    //  6,400,000
static constexpr unsigned C1 = (unsigned)(B * D / 4);    //      8,192
static constexpr unsigned C2 = (unsigned)(E / 4);        //    800,000
static constexpr unsigned C3 = (unsigned)(N / 4);        //     25,000
static constexpr unsigned C4 = C2;
static constexpr unsigned C5 = C3;
static constexpr unsigned C6 = (unsigned)(E * De / 4);   // 25,600,000
static constexpr unsigned C7 = (unsigned)(N * De / 4);   //    800,000
static constexpr unsigned C8 = C3;
static constexpr unsigned C9 = (unsigned)(B / 4);        //         32

// Output bases (prefix sums, float4 units) — all < 2^32
static constexpr unsigned O0 = 0;
static constexpr unsigned O1 = O0 + C0;
static constexpr unsigned O2 = O1 + C1;
static constexpr unsigned O3 = O2 + C2;
static constexpr unsigned O4 = O3 + C3;
static constexpr unsigned O5 = O4 + C4;
static constexpr unsigned O6 = O5 + C5;
static constexpr unsigned O7 = O6 + C6;
static constexpr unsigned O8 = O7 + C7;
static constexpr unsigned O9 = O8 + C8;

static constexpr int T = 256;
static constexpr int UNROLL = 4;
static constexpr unsigned CPB = T * UNROLL;  // 1024 chunks per block

static constexpr unsigned cdivu(unsigned a, unsigned b) { return (a + b - 1) / b; }
static constexpr unsigned B0 = cdivu(C0, CPB);
static constexpr unsigned B1 = cdivu(C1, CPB);
static constexpr unsigned B2 = cdivu(C2, CPB);
static constexpr unsigned B3 = cdivu(C3, CPB);
static constexpr unsigned B4 = cdivu(C4, CPB);
static constexpr unsigned B5 = cdivu(C5, CPB);
static constexpr unsigned B6 = cdivu(C6, CPB);
static constexpr unsigned B7 = cdivu(C7, CPB);
static constexpr unsigned B8 = cdivu(C8, CPB);
static constexpr unsigned B9 = cdivu(C9, CPB);
static constexpr unsigned P1 = B0;
static constexpr unsigned P2 = P1 + B1;
static constexpr unsigned P3 = P2 + B2;
static constexpr unsigned P4 = P3 + B3;
static constexpr unsigned P5 = P4 + B4;
static constexpr unsigned P6 = P5 + B5;
static constexpr unsigned P7 = P6 + B6;
static constexpr unsigned P8 = P7 + B7;
static constexpr unsigned P9 = P8 + B8;
static constexpr unsigned P_END = P9 + B9;

// Branch-free region bodies. c0 = region-local first chunk for this thread.
// nch = region chunk count; all u32. Guards also clamp to the real out_size.

__device__ __forceinline__ void do_copy(
    const float4* __restrict__ src, float4* __restrict__ dst,
    unsigned c0, unsigned nch, unsigned glim)
{
    unsigned c[UNROLL]; bool ok[UNROLL]; float4 v[UNROLL];
#pragma unroll
    for (int k = 0; k < UNROLL; k++) { c[k] = c0 + k * T; ok[k] = c[k] < nch && c[k] < glim; }
#pragma unroll
    for (int k = 0; k < UNROLL; k++) if (ok[k]) v[k] = __ldcs(src + c[k]);
#pragma unroll
    for (int k = 0; k < UNROLL; k++) if (ok[k]) __stcs(dst + c[k], v[k]);
}

__device__ __forceinline__ void do_zero(
    float4* __restrict__ dst, unsigned c0, unsigned nch, unsigned glim)
{
    const float4 z = make_float4(0.f, 0.f, 0.f, 0.f);
#pragma unroll
    for (int k = 0; k < UNROLL; k++) {
        unsigned c = c0 + k * T;
        if (c < nch && c < glim) __stcs(dst + c, z);
    }
}

__device__ __forceinline__ void do_cvt(
    const int4* __restrict__ src, float4* __restrict__ dst,
    unsigned c0, unsigned nch, unsigned glim, int bias)
{
    unsigned c[UNROLL]; bool ok[UNROLL]; int4 a[UNROLL];
#pragma unroll
    for (int k = 0; k < UNROLL; k++) { c[k] = c0 + k * T; ok[k] = c[k] < nch && c[k] < glim; }
#pragma unroll
    for (int k = 0; k < UNROLL; k++) if (ok[k]) a[k] = __ldcs(src + c[k]);
#pragma unroll
    for (int k = 0; k < UNROLL; k++) if (ok[k]) {
        float4 v = make_float4((float)(a[k].x + bias), (float)(a[k].y + bias),
                               (float)(a[k].z + bias), (float)(a[k].w + bias));
        __stcs(dst + c[k], v);
    }
}

__device__ __forceinline__ void do_arange(
    float4* __restrict__ dst, unsigned c0, unsigned nch, unsigned glim)
{
#pragma unroll
    for (int k = 0; k < UNROLL; k++) {
        unsigned c = c0 + k * T;
        if (c < nch && c < glim) {
            float f = (float)(4u * c);
            __stcs(dst + c, make_float4(f, f + 1.f, f + 2.f, f + 3.f));
        }
    }
}

__global__ void __launch_bounds__(T) vnode_fused_kernel(
    const float* __restrict__ x, const int* __restrict__ ei,
    const float* __restrict__ ea, const int* __restrict__ batch,
    float* __restrict__ out, unsigned lim4)
{
    const unsigned b = blockIdx.x;
    float4* o4 = (float4*)out;

    // Scalar region dispatch (all constants fold to immediates). Ordered so the
    // two big copy regions resolve first.
    if (b >= P6 && b < P7) {          // ea copy — 74% of blocks
        unsigned c0 = (b - P6) * CPB + threadIdx.x;
        do_copy((const float4*)ea, o4 + O6, c0, C6, lim4 - O6);
    } else if (b < P1) {              // x copy — 19%
        unsigned c0 = b * CPB + threadIdx.x;
        do_copy((const float4*)x, o4 + O0, c0, C0, lim4 - O0);
    } else if (b < P2) {              // x virtual-node zeros
        unsigned c0 = (b - P1) * CPB + threadIdx.x;
        do_zero(o4 + O1, c0, C1, lim4 - O1);
    } else if (b < P3) {              // ei row 0 cvt
        unsigned c0 = (b - P2) * CPB + threadIdx.x;
        do_cvt((const int4*)ei, o4 + O2, c0, C2, lim4 - O2, 0);
    } else if (b < P4) {              // heads = arange(N)
        unsigned c0 = (b - P3) * CPB + threadIdx.x;
        do_arange(o4 + O3, c0, C3, lim4 - O3);
    } else if (b < P5) {              // ei row 1 cvt
        unsigned c0 = (b - P4) * CPB + threadIdx.x;
        do_cvt((const int4*)(ei + E), o4 + O4, c0, C4, lim4 - O4, 0);
    } else if (b < P6) {              // tails = N + batch
        unsigned c0 = (b - P5) * CPB + threadIdx.x;
        do_cvt((const int4*)batch, o4 + O5, c0, C5, lim4 - O5, (int)N);
    } else if (b < P8) {              // ea virtual-edge zeros
        unsigned c0 = (b - P7) * CPB + threadIdx.x;
        do_zero(o4 + O7, c0, C7, lim4 - O7);
    } else if (b < P9) {              // new_batch head = batch cast
        unsigned c0 = (b - P8) * CPB + threadIdx.x;
        do_cvt((const int4*)batch, o4 + O8, c0, C8, lim4 - O8, 0);
    } else {                          // arange(B)
        unsigned c0 = (b - P9) * CPB + threadIdx.x;
        do_arange(o4 + O9, c0, C9, lim4 - O9);
    }
}

extern "C" void kernel_launch(void* const* d_in, const int* in_sizes, int n_in,
                              void* d_out, int out_size) {
    const float* x     = (const float*)d_in[0];
    const int*   ei    = (const int*)d_in[1];
    const float* ea    = (const float*)d_in[2];
    const int*   batch = (const int*)d_in[3];
    float* out = (float*)d_out;

    unsigned lim4 = (unsigned)(out_size / 4);  // whole float4s in d_out
    vnode_fused_kernel<<<P_END, T>>>(x, ei, ea, batch, out, lim4);
}